// round 6
// baseline (speedup 1.0000x reference)
#include <cuda_runtime.h>

// RelateBatch: one-hot block structure of batch_object_map (obj_q = n//8)
// collapses both einsum chains to per-8x8 diagonal-block row/col reductions.
// Reads 8.4 MB instead of 537 MB.
// Round 6: maximize warp-level latency hiding — 4096 CTAs x 64 thr (8192
// warps, ~86% occ ceiling), thread-per-cell (MLP=2), warp-local row sums,
// 16-float smem exchange for cross-warp col sums.

#define EPSF 1e-12f

__device__ __forceinline__ float pnotf(float x, float a) {
    // a * log(max(1 - exp(min(x,0)), EPS)) + (1-a) * x
    float xm = fminf(x, 0.0f);
    float e  = __expf(xm);
    float l  = __logf(fmaxf(1.0f - e, EPSF));
    return fmaf(a, l, (1.0f - a) * x);
}

__global__ __launch_bounds__(64) void relate_batch_kernel(
    const float* __restrict__ log_prior,   // (64, 2, 512)
    const float* __restrict__ loglik,      // (64, 512, 512, 8)
    const float* __restrict__ quant,       // (64, 2)
    float* __restrict__ out)               // (64, 2, 512)
{
    constexpr unsigned N = 512;
    const unsigned p    = blockIdx.y;                 // 0..63
    const unsigned g    = blockIdx.x;                 // 0..63 (tile)
    const unsigned wid  = threadIdx.x >> 5;           // 0..1
    const unsigned lane = threadIdx.x & 31u;
    const unsigned i    = wid * 4u + (lane >> 3);     // row 0..7
    const unsigned j    = lane & 7u;                  // col 0..7
    const unsigned n    = g * 8u + i;
    const unsigned m    = g * 8u + j;

    __shared__ float spart[2][8];                     // per-warp col partials

    // One cell = 8 contiguous floats (32B): two independent LDG.128.
    const unsigned base = ((p * N + n) * N + m) * 8u;
    float4 u = __ldcs(reinterpret_cast<const float4*>(loglik + base));
    float4 v4 = __ldcs(reinterpret_cast<const float4*>(loglik + base + 4u));

    const float q0 = quant[2u * p + 0u];
    const float q1 = quant[2u * p + 1u];
    const float lp0_n = log_prior[(p * 2u + 0u) * N + n];
    const float lp1_m = log_prior[(p * 2u + 1u) * N + m];

    float s = ((u.x + u.y) + (u.z + u.w)) + ((v4.x + v4.y) + (v4.z + v4.w));
    float llv = fminf(s * 0.125f, 0.0f);              // min(mean_f, 0)

    const float dmask = (i == j) ? 0.0f : 1.0f;       // off_diag
    float v = dmask * pnotf(llv + lp1_m, q1);         // row path (out0)
    float w = dmask * pnotf(llv + lp0_n, q0);         // col path (out1)

    // Row sums: butterfly over the 8-lane j-group (row fully inside warp).
    #pragma unroll
    for (int d = 1; d < 8; d <<= 1)
        v += __shfl_xor_sync(0xffffffffu, v, d);
    if (j == 0u)
        out[(p * 2u + 0u) * N + n] = pnotf(v, q1) + lp0_n;

    // Col partial sums over this warp's 4 rows.
    w += __shfl_xor_sync(0xffffffffu, w, 8);
    w += __shfl_xor_sync(0xffffffffu, w, 16);
    if (lane < 8u) spart[wid][j] = w;
    __syncthreads();

    if (threadIdx.x < 8u) {
        float cs = spart[0][j] + spart[1][j];
        out[(p * 2u + 1u) * N + m] = pnotf(cs, q0) + lp1_m;
    }
}

extern "C" void kernel_launch(void* const* d_in, const int* in_sizes, int n_in,
                              void* d_out, int out_size) {
    const float* log_prior = (const float*)d_in[0];   // (64,2,512)
    const float* loglik    = (const float*)d_in[1];   // (64,512,512,8)
    const float* quant     = (const float*)d_in[2];   // (64,2)
    float* out = (float*)d_out;                       // (64,2,512)

    dim3 grid(64, 64);   // tile g x batch p = 4096 CTAs, 2 warps each
    dim3 block(64);
    relate_batch_kernel<<<grid, block>>>(log_prior, loglik, quant, out);
}

// round 7
// speedup vs baseline: 1.3413x; 1.3413x over previous
#include <cuda_runtime.h>

// RelateBatch: one-hot block structure of batch_object_map (obj_q = n//8)
// collapses both einsum chains to per-8x8 diagonal-block row/col reductions.
// Reads 8.4 MB instead of 537 MB.
// Round 7: dense-sector loads. 16 lanes cover one 256B row slice (each lane
// one float4 = half a cell), so every LDG.128 moves 512B at 100% sector
// utilization. Warp = tile, 4 LDG.128/thread (rows rh,rh+2,rh+4,rh+6),
// 4096 warps in 1024 CTAs of 128 threads.

#define EPSF 1e-12f

__device__ __forceinline__ float pnotf(float x, float a) {
    // a * log(max(1 - exp(min(x,0)), EPS)) + (1-a) * x
    float xm = fminf(x, 0.0f);
    float e  = __expf(xm);
    float l  = __logf(fmaxf(1.0f - e, EPSF));
    return fmaf(a, l, (1.0f - a) * x);
}

__global__ __launch_bounds__(128) void relate_batch_kernel(
    const float* __restrict__ log_prior,   // (64, 2, 512)
    const float* __restrict__ loglik,      // (64, 512, 512, 8)
    const float* __restrict__ quant,       // (64, 2)
    float* __restrict__ out)               // (64, 2, 512)
{
    constexpr unsigned N = 512;
    const unsigned p    = blockIdx.y;                       // 0..63
    const unsigned g    = blockIdx.x * 4u + (threadIdx.x >> 5); // tile 0..63
    const unsigned lane = threadIdx.x & 31u;
    const unsigned rh   = lane >> 4;                        // row parity 0/1
    const unsigned c    = lane & 15u;                       // 16B chunk in row
    const unsigned ml   = c >> 1;                           // local col 0..7
    const unsigned m    = g * 8u + ml;                      // column object

    const float q0 = quant[2u * p + 0u];
    const float q1 = quant[2u * p + 1u];
    const float lp1_m = log_prior[(p * 2u + 1u) * N + m];

    // Rows handled by this lane: rh, rh+2, rh+4, rh+6 within the tile.
    // Each LDG.128: 32 lanes read 2 full 256B row slices, dense sectors.
    float4 d[4];
    #pragma unroll
    for (int k = 0; k < 4; k++) {
        const unsigned row = rh + 2u * k;
        const unsigned base = ((p * N + g * 8u + row) * N + g * 8u) * 8u + c * 4u;
        d[k] = __ldcs(reinterpret_cast<const float4*>(loglik + base));
    }

    float lp0r[4];
    #pragma unroll
    for (int k = 0; k < 4; k++)
        lp0r[k] = log_prior[(p * 2u + 0u) * N + g * 8u + rh + 2u * k];

    // ll per (row k, cell m): half-cell sum + partner-lane half via xor(1).
    float rs[4];        // row-path accumulators (per k)
    float wl = 0.0f;    // col-path accumulator over this lane's 4 rows
    #pragma unroll
    for (int k = 0; k < 4; k++) {
        float h = ((d[k].x + d[k].y) + (d[k].z + d[k].w));
        float full = h + __shfl_xor_sync(0xffffffffu, h, 1);
        float llv = fminf(full * 0.125f, 0.0f);
        const unsigned row = rh + 2u * k;
        float dm = (row == ml) ? 0.0f : 1.0f;
        rs[k] = dm * pnotf(llv + lp1_m, q1);
        wl   += dm * pnotf(llv + lp0r[k], q0);
    }

    // Row sums: butterfly over xor {2,4,8} sums cells m=0..7 exactly once
    // (values duplicated across the c&1 halves, so spans of same parity
    // cover all 8 distinct cells).
    #pragma unroll
    for (int dd = 2; dd < 16; dd <<= 1) {
        #pragma unroll
        for (int k = 0; k < 4; k++)
            rs[k] += __shfl_xor_sync(0xffffffffu, rs[k], dd);
    }
    if (c == 0u) {
        #pragma unroll
        for (int k = 0; k < 4; k++) {
            const unsigned n = g * 8u + rh + 2u * k;
            out[(p * 2u + 0u) * N + n] = pnotf(rs[k], q1) + lp0r[k];
        }
    }

    // Col sums: add the other row-parity half (xor 16) -> sum over 8 rows.
    wl += __shfl_xor_sync(0xffffffffu, wl, 16);
    if (rh == 0u && (c & 1u) == 0u) {
        out[(p * 2u + 1u) * N + m] = pnotf(wl, q0) + lp1_m;
    }
}

extern "C" void kernel_launch(void* const* d_in, const int* in_sizes, int n_in,
                              void* d_out, int out_size) {
    const float* log_prior = (const float*)d_in[0];   // (64,2,512)
    const float* loglik    = (const float*)d_in[1];   // (64,512,512,8)
    const float* quant     = (const float*)d_in[2];   // (64,2)
    float* out = (float*)d_out;                       // (64,2,512)

    dim3 grid(16, 64);   // 16 tile-quads x 64 batches = 1024 CTAs (4 warps ea)
    dim3 block(128);
    relate_batch_kernel<<<grid, block>>>(log_prior, loglik, quant, out);
}

// round 8
// speedup vs baseline: 1.3544x; 1.0097x over previous
#include <cuda_runtime.h>
#include <cuda.h>
#include <cstdint>

// RelateBatch: one-hot block structure of batch_object_map (obj_q = n//8)
// collapses both einsum chains to per-8x8 diagonal-block row/col reductions.
// Reads 8.4 MB instead of 537 MB.
// Round 8: TMA bulk tile fetch. One cp.async.bulk.tensor.3d per 8x8 tile
// (box 64 floats x 8 rows x 1) replaces 16 scattered LDG.128 — the TMA
// engine supplies requests at the LTS cap instead of the per-warp LSU path.
// Compute per warp = round-3 shuffle reduction (proven). LDG fallback kernel
// if the driver entry point for tensor-map encode is unavailable.

#define EPSF 1e-12f

__device__ __forceinline__ float pnotf(float x, float a) {
    float xm = fminf(x, 0.0f);
    float e  = __expf(xm);
    float l  = __logf(fmaxf(1.0f - e, EPSF));
    return fmaf(a, l, (1.0f - a) * x);
}

__device__ __forceinline__ uint32_t smem_u32(const void* p) {
    return (uint32_t)__cvta_generic_to_shared(p);
}

// ---------------------------------------------------------------- TMA kernel
__global__ __launch_bounds__(128) void relate_tma_kernel(
    const __grid_constant__ CUtensorMap tmap,   // loglik as (4096, 512, 64)
    const float* __restrict__ log_prior,        // (64, 2, 512)
    const float* __restrict__ quant,            // (64, 2)
    float* __restrict__ out)                    // (64, 2, 512)
{
    constexpr unsigned N = 512;
    __shared__ __align__(1024) float tiles[4][512];   // 4 tiles x 2KB
    __shared__ __align__(8) uint64_t mbar;

    const unsigned p   = blockIdx.y;            // 0..63
    const unsigned g0  = blockIdx.x * 4u;       // first tile of this CTA
    const unsigned tid = threadIdx.x;
    const uint32_t bar = smem_u32(&mbar);

    if (tid == 0) {
        asm volatile("mbarrier.init.shared.b64 [%0], %1;"
                     :: "r"(bar), "r"(1u) : "memory");
    }
    __syncthreads();

    if (tid == 0) {
        asm volatile("mbarrier.arrive.expect_tx.shared.b64 _, [%0], %1;"
                     :: "r"(bar), "r"(8192u) : "memory");
        #pragma unroll
        for (unsigned t = 0; t < 4; t++) {
            const unsigned g = g0 + t;
            const uint32_t dst = smem_u32(&tiles[t][0]);
            asm volatile(
                "cp.async.bulk.tensor.3d.shared::cta.global.tile"
                ".mbarrier::complete_tx::bytes [%0], [%1, {%2, %3, %4}], [%5];"
                :: "r"(dst), "l"(&tmap),
                   "r"((int)(g * 64u)), "r"((int)(g * 8u)), "r"((int)p),
                   "r"(bar)
                : "memory");
        }
    }

    // All threads wait (acquire) for the 8KB of tile data.
    {
        uint32_t done;
        asm volatile(
            "{\n\t.reg .pred pd;\n\t"
            "mbarrier.try_wait.parity.acquire.cta.shared::cta.b64 pd, [%1], 0;\n\t"
            "selp.b32 %0, 1, 0, pd;\n\t}"
            : "=r"(done) : "r"(bar) : "memory");
        if (!done) {
            asm volatile(
                "{\n\t.reg .pred P1;\n\t"
                "WL_%=:\n\t"
                "mbarrier.try_wait.parity.acquire.cta.shared::cta.b64 P1, [%0], 0, 0x989680;\n\t"
                "@P1 bra.uni WD_%=;\n\t"
                "bra.uni WL_%=;\n\t"
                "WD_%=:\n\t}"
                :: "r"(bar) : "memory");
        }
    }

    // Per-warp compute: warp wid owns tile g0+wid (round-3 mapping).
    const unsigned wid  = tid >> 5;
    const unsigned lane = tid & 31u;
    const unsigned i0   = lane >> 3;        // 0..3
    const unsigned j    = lane & 7u;        // 0..7
    const unsigned r0   = i0;
    const unsigned r1   = i0 + 4u;
    const unsigned g    = g0 + wid;
    const unsigned m    = g * 8u + j;
    const float* tb = tiles[wid];

    const float q0 = quant[2u * p + 0u];
    const float q1 = quant[2u * p + 1u];
    const float lp0_r0 = log_prior[(p * 2u + 0u) * N + g * 8u + r0];
    const float lp0_r1 = log_prior[(p * 2u + 0u) * N + g * 8u + r1];
    const float lp1_m  = log_prior[(p * 2u + 1u) * N + m];

    float4 a0 = *reinterpret_cast<const float4*>(tb + r0 * 64u + j * 8u);
    float4 a1 = *reinterpret_cast<const float4*>(tb + r0 * 64u + j * 8u + 4u);
    float4 c0 = *reinterpret_cast<const float4*>(tb + r1 * 64u + j * 8u);
    float4 c1 = *reinterpret_cast<const float4*>(tb + r1 * 64u + j * 8u + 4u);

    float llv0 = fminf((((a0.x + a0.y) + (a0.z + a0.w)) +
                        ((a1.x + a1.y) + (a1.z + a1.w))) * 0.125f, 0.0f);
    float llv1 = fminf((((c0.x + c0.y) + (c0.z + c0.w)) +
                        ((c1.x + c1.y) + (c1.z + c1.w))) * 0.125f, 0.0f);

    const float d0 = (r0 == j) ? 0.0f : 1.0f;
    const float d1 = (r1 == j) ? 0.0f : 1.0f;

    float v0 = d0 * pnotf(llv0 + lp1_m, q1);
    float v1 = d1 * pnotf(llv1 + lp1_m, q1);
    float w0 = d0 * pnotf(llv0 + lp0_r0, q0);
    float w1 = d1 * pnotf(llv1 + lp0_r1, q0);

    #pragma unroll
    for (int d = 1; d < 8; d <<= 1) {
        v0 += __shfl_xor_sync(0xffffffffu, v0, d);
        v1 += __shfl_xor_sync(0xffffffffu, v1, d);
    }
    float wc = w0 + w1;
    wc += __shfl_xor_sync(0xffffffffu, wc, 8);
    wc += __shfl_xor_sync(0xffffffffu, wc, 16);

    if (j == 0u) {
        out[(p * 2u + 0u) * N + g * 8u + r0] = pnotf(v0, q1) + lp0_r0;
        out[(p * 2u + 0u) * N + g * 8u + r1] = pnotf(v1, q1) + lp0_r1;
    }
    if (i0 == 0u) {
        out[(p * 2u + 1u) * N + m] = pnotf(wc, q0) + lp1_m;
    }
}

// ------------------------------------------------------ fallback LDG kernel
__global__ __launch_bounds__(128) void relate_batch_kernel(
    const float* __restrict__ log_prior,
    const float* __restrict__ loglik,
    const float* __restrict__ quant,
    float* __restrict__ out)
{
    constexpr unsigned N = 512;
    const unsigned p    = blockIdx.y;
    const unsigned g    = blockIdx.x * 4u + (threadIdx.x >> 5);
    const unsigned lane = threadIdx.x & 31u;
    const unsigned rh   = lane >> 4;
    const unsigned c    = lane & 15u;
    const unsigned ml   = c >> 1;
    const unsigned m    = g * 8u + ml;

    const float q0 = quant[2u * p + 0u];
    const float q1 = quant[2u * p + 1u];
    const float lp1_m = log_prior[(p * 2u + 1u) * N + m];

    float4 d[4];
    #pragma unroll
    for (int k = 0; k < 4; k++) {
        const unsigned row = rh + 2u * k;
        const unsigned base = ((p * N + g * 8u + row) * N + g * 8u) * 8u + c * 4u;
        d[k] = __ldcs(reinterpret_cast<const float4*>(loglik + base));
    }
    float lp0r[4];
    #pragma unroll
    for (int k = 0; k < 4; k++)
        lp0r[k] = log_prior[(p * 2u + 0u) * N + g * 8u + rh + 2u * k];

    float rs[4];
    float wl = 0.0f;
    #pragma unroll
    for (int k = 0; k < 4; k++) {
        float h = ((d[k].x + d[k].y) + (d[k].z + d[k].w));
        float full = h + __shfl_xor_sync(0xffffffffu, h, 1);
        float llv = fminf(full * 0.125f, 0.0f);
        const unsigned row = rh + 2u * k;
        float dm = (row == ml) ? 0.0f : 1.0f;
        rs[k] = dm * pnotf(llv + lp1_m, q1);
        wl   += dm * pnotf(llv + lp0r[k], q0);
    }
    #pragma unroll
    for (int dd = 2; dd < 16; dd <<= 1) {
        #pragma unroll
        for (int k = 0; k < 4; k++)
            rs[k] += __shfl_xor_sync(0xffffffffu, rs[k], dd);
    }
    if (c == 0u) {
        #pragma unroll
        for (int k = 0; k < 4; k++) {
            const unsigned n = g * 8u + rh + 2u * k;
            out[(p * 2u + 0u) * N + n] = pnotf(rs[k], q1) + lp0r[k];
        }
    }
    wl += __shfl_xor_sync(0xffffffffu, wl, 16);
    if (rh == 0u && (c & 1u) == 0u) {
        out[(p * 2u + 1u) * N + m] = pnotf(wl, q0) + lp1_m;
    }
}

// ---------------------------------------------------------------- host side
typedef CUresult (*EncodeTiledFn)(
    CUtensorMap*, CUtensorMapDataType, cuuint32_t, void*,
    const cuuint64_t*, const cuuint64_t*, const cuuint32_t*, const cuuint32_t*,
    CUtensorMapInterleave, CUtensorMapSwizzle, CUtensorMapL2promotion,
    CUtensorMapFloatOOBfill);

extern "C" void kernel_launch(void* const* d_in, const int* in_sizes, int n_in,
                              void* d_out, int out_size) {
    const float* log_prior = (const float*)d_in[0];   // (64,2,512)
    const float* loglik    = (const float*)d_in[1];   // (64,512,512,8)
    const float* quant     = (const float*)d_in[2];   // (64,2)
    float* out = (float*)d_out;                       // (64,2,512)

    // Try to build the tensor map (host-only; runs at capture time under
    // graph replay, so its cost is not timed).
    void* fn = nullptr;
    cudaDriverEntryPointQueryResult qr = cudaDriverEntryPointSymbolNotFound;
    cudaGetDriverEntryPoint("cuTensorMapEncodeTiled", &fn,
                            cudaEnableDefault, &qr);

    bool tma_ok = false;
    CUtensorMap tmap;
    if (fn && qr == cudaDriverEntryPointSuccess) {
        // View loglik (64,512,512,8) f32 as 3D: x = 4096 floats per n-row,
        // y = n (512, stride 16KB), z = p (64, stride 8.39MB).
        cuuint64_t dims[3]    = {4096ull, 512ull, 64ull};
        cuuint64_t strides[2] = {4096ull * 4ull, 512ull * 4096ull * 4ull};
        cuuint32_t box[3]     = {64u, 8u, 1u};
        cuuint32_t estr[3]    = {1u, 1u, 1u};
        CUresult r = ((EncodeTiledFn)fn)(
            &tmap, CU_TENSOR_MAP_DATA_TYPE_FLOAT32, 3, (void*)loglik,
            dims, strides, box, estr,
            CU_TENSOR_MAP_INTERLEAVE_NONE, CU_TENSOR_MAP_SWIZZLE_NONE,
            CU_TENSOR_MAP_L2_PROMOTION_L2_128B,
            CU_TENSOR_MAP_FLOAT_OOB_FILL_NONE);
        tma_ok = (r == CUDA_SUCCESS);
    }

    dim3 grid(16, 64);
    dim3 block(128);
    if (tma_ok) {
        relate_tma_kernel<<<grid, block>>>(tmap, log_prior, quant, out);
    } else {
        relate_batch_kernel<<<grid, block>>>(log_prior, loglik, quant, out);
    }
}